// round 14
// baseline (speedup 1.0000x reference)
#include <cuda_runtime.h>
#include <cuda_bf16.h>
#include <math.h>

#define L_TOK 131072
#define C_DIM 192
#define QKV_DIM 576
#define FF_DIM 768
#define NWIN 2048

typedef __nv_bfloat16 bf16;

// scratch (device globals)
__device__ bf16 g_bufA[(size_t)L_TOK * C_DIM];   // LN out (bf16)
__device__ bf16 g_qkv [(size_t)L_TOK * QKV_DIM]; // QKV (bf16)
__device__ bf16 g_obuf[(size_t)L_TOK * C_DIM];   // attn out (bf16)
__device__ bf16 g_bufT[(size_t)L_TOK * FF_DIM];  // MLP hidden (bf16)
__device__ bf16 g_wbf [884736];                  // bf16 weights [K,N]

__device__ __forceinline__ void cp_async16(void* smem, const void* gmem) {
    unsigned saddr = (unsigned)__cvta_generic_to_shared(smem);
    asm volatile("cp.async.cg.shared.global [%0], [%1], 16;\n" :: "r"(saddr), "l"(gmem));
}
__device__ __forceinline__ void ldsm_x4(unsigned& r0, unsigned& r1,
                                        unsigned& r2, unsigned& r3, unsigned addr) {
    asm volatile("ldmatrix.sync.aligned.m8n8.x4.shared.b16 {%0,%1,%2,%3}, [%4];"
                 : "=r"(r0), "=r"(r1), "=r"(r2), "=r"(r3) : "r"(addr));
}
__device__ __forceinline__ void ldsm_x4_t(unsigned& r0, unsigned& r1,
                                          unsigned& r2, unsigned& r3, unsigned addr) {
    asm volatile("ldmatrix.sync.aligned.m8n8.x4.trans.shared.b16 {%0,%1,%2,%3}, [%4];"
                 : "=r"(r0), "=r"(r1), "=r"(r2), "=r"(r3) : "r"(addr));
}
__device__ __forceinline__ void mma16816(float* c, unsigned a0, unsigned a1,
                                         unsigned a2, unsigned a3,
                                         unsigned b0, unsigned b1) {
    asm volatile(
        "mma.sync.aligned.m16n8k16.row.col.f32.bf16.bf16.f32 "
        "{%0,%1,%2,%3},{%4,%5,%6,%7},{%8,%9},{%0,%1,%2,%3};"
        : "+f"(c[0]), "+f"(c[1]), "+f"(c[2]), "+f"(c[3])
        : "r"(a0), "r"(a1), "r"(a2), "r"(a3), "r"(b0), "r"(b1));
}

// ---------------------------------------------------------------------------
// Fused weight conversion
// ---------------------------------------------------------------------------
struct WcvtArgs {
    const float* src[8];
    int off[9];
};

__global__ void cvt_weights_kernel(WcvtArgs a, bf16* __restrict__ out)
{
    int i = blockIdx.x * 256 + threadIdx.x;
    if (i >= a.off[8]) return;
    int s = 0;
#pragma unroll
    for (int j = 1; j < 8; j++) s += (i >= a.off[j]);
    out[i] = __float2bfloat16(a.src[s][i - a.off[s]]);
}

// ---------------------------------------------------------------------------
// LayerNorm, one row per warp; bf16 output
// ---------------------------------------------------------------------------
__global__ void ln_kernel(const float* __restrict__ x,
                          const float* __restrict__ g,
                          const float* __restrict__ b,
                          bf16* __restrict__ out)
{
    int row  = blockIdx.x * 8 + threadIdx.y;
    int lane = threadIdx.x;
    const float* xr = x + (size_t)row * C_DIM;
    float v[6];
    float s = 0.f;
#pragma unroll
    for (int i = 0; i < 6; i++) { v[i] = xr[lane + i * 32]; s += v[i]; }
#pragma unroll
    for (int o = 16; o; o >>= 1) s += __shfl_xor_sync(0xffffffffu, s, o);
    float mu = s * (1.0f / 192.0f);
    float vs = 0.f;
#pragma unroll
    for (int i = 0; i < 6; i++) { float d = v[i] - mu; vs += d * d; }
#pragma unroll
    for (int o = 16; o; o >>= 1) vs += __shfl_xor_sync(0xffffffffu, vs, o);
    float rstd = rsqrtf(vs * (1.0f / 192.0f) + 1e-5f);
    bf16* orow = out + (size_t)row * C_DIM;
#pragma unroll
    for (int i = 0; i < 6; i++) {
        int c = lane + i * 32;
        orow[c] = __float2bfloat16((v[i] - mu) * rstd * g[c] + b[c]);
    }
}

// ---------------------------------------------------------------------------
// bf16 GEMM: BM=128, BN=192, BK=64. 256 thr, 8 warps (4m x 2n),
// warp tile 32x96. 2-stage cp.async, dynamic smem 88 KB, 2 CTAs/SM.
// ---------------------------------------------------------------------------
#define GBM 128
#define GBN 192
#define GBK 64
#define ASTRH 72                      // 64 + 8 pad (bf16)
#define BSTRH 200                     // 192 + 8 pad (bf16)
#define ABYTES (GBM * ASTRH * 2)      // 18432
#define BBYTES (GBK * BSTRH * 2)      // 25600
#define STAGEB (ABYTES + BBYTES)      // 44032
#define GSMEM  (2 * STAGEB)           // 88064

template<bool DOGELU, bool RES, bool OUTBF>
__global__ __launch_bounds__(256, 2)
void gemm_bf16(const bf16* __restrict__ A, const bf16* __restrict__ B,
               const float* __restrict__ bias, const float* __restrict__ res,
               void* __restrict__ Cout, int M, int N, int K)
{
    extern __shared__ char smem[];

    int tid = threadIdx.x;
    int bm = blockIdx.y * GBM;
    int bn = blockIdx.x * GBN;
    int wid = tid >> 5, lane = tid & 31;
    int wm = (wid & 3) * 32, wn = (wid >> 2) * 96;
    int g = lane >> 2, t = lane & 3;

    int ldrow = (lane & 7) + ((lane >> 3) & 1) * 8;
    int ldcol = (lane >> 4) * 8;

    unsigned s0 = (unsigned)__cvta_generic_to_shared(smem);
    unsigned aBase = s0 + (unsigned)(((wm + ldrow) * ASTRH + ldcol) * 2);
    unsigned bBase = s0 + (unsigned)(ABYTES + (ldrow * BSTRH + wn + ldcol) * 2);

    float acc[2][12][4];
#pragma unroll
    for (int a = 0; a < 2; a++)
#pragma unroll
        for (int j = 0; j < 12; j++)
#pragma unroll
            for (int c = 0; c < 4; c++) acc[a][j][c] = 0.f;

    auto loadA = [&](int stage, int k0) {
        // 128 rows x 8 chunks(8 bf16) = 1024 -> 4 per thread
#pragma unroll
        for (int l = 0; l < 4; l++) {
            int idx = tid + l * 256;
            int m = idx >> 3;
            int c = (idx & 7) * 8;
            cp_async16(smem + stage * STAGEB + (m * ASTRH + c) * 2,
                       A + (size_t)(bm + m) * K + k0 + c);
        }
    };
    auto loadB = [&](int stage, int k0) {
        // 64 rows x 24 chunks = 1536 -> 6 per thread
#pragma unroll
        for (int l = 0; l < 6; l++) {
            int idx = tid + l * 256;
            int r = idx / 24;
            int c = (idx % 24) * 8;
            cp_async16(smem + stage * STAGEB + ABYTES + (r * BSTRH + c) * 2,
                       B + (size_t)(k0 + r) * N + bn + c);
        }
    };

    int nk = K / GBK;
    loadA(0, 0); loadB(0, 0);
    asm volatile("cp.async.commit_group;");
    if (nk > 1) { loadA(1, GBK); loadB(1, GBK); }
    asm volatile("cp.async.commit_group;");

    for (int kb = 0; kb < nk; kb++) {
        if (kb + 1 < nk) { asm volatile("cp.async.wait_group 1;"); }
        else             { asm volatile("cp.async.wait_group 0;"); }
        __syncthreads();

        int st = kb & 1;
        unsigned aS = aBase + st * STAGEB;
        unsigned bS = bBase + st * STAGEB;
#pragma unroll
        for (int ks = 0; ks < 4; ks++) {
            unsigned af[2][4], bfr[6][4];
#pragma unroll
            for (int mt = 0; mt < 2; mt++)
                ldsm_x4(af[mt][0], af[mt][1], af[mt][2], af[mt][3],
                        aS + mt * (16 * ASTRH * 2) + ks * 32);
#pragma unroll
            for (int nt = 0; nt < 6; nt++)
                ldsm_x4_t(bfr[nt][0], bfr[nt][1], bfr[nt][2], bfr[nt][3],
                          bS + ks * (16 * BSTRH * 2) + nt * 32);
#pragma unroll
            for (int mt = 0; mt < 2; mt++)
#pragma unroll
                for (int nt = 0; nt < 6; nt++) {
                    mma16816(acc[mt][nt * 2],     af[mt][0], af[mt][1],
                             af[mt][2], af[mt][3], bfr[nt][0], bfr[nt][1]);
                    mma16816(acc[mt][nt * 2 + 1], af[mt][0], af[mt][1],
                             af[mt][2], af[mt][3], bfr[nt][2], bfr[nt][3]);
                }
        }
        __syncthreads();

        if (kb + 2 < nk) {
            loadA(kb & 1, (kb + 2) * GBK);
            loadB(kb & 1, (kb + 2) * GBK);
        }
        asm volatile("cp.async.commit_group;");
    }

#pragma unroll
    for (int mt = 0; mt < 2; mt++)
#pragma unroll
        for (int j = 0; j < 12; j++) {
            int col = bn + wn + j * 8 + 2 * t;
            float2 bv = *(const float2*)(bias + col);
#pragma unroll
            for (int hf = 0; hf < 2; hf++) {
                int row = bm + wm + mt * 16 + g + hf * 8;
                float x0 = acc[mt][j][hf * 2 + 0] + bv.x;
                float x1 = acc[mt][j][hf * 2 + 1] + bv.y;
                if (DOGELU) {
                    x0 = 0.5f * x0 * (1.0f + erff(x0 * 0.70710678118654752f));
                    x1 = 0.5f * x1 * (1.0f + erff(x1 * 0.70710678118654752f));
                }
                if (RES) {
                    float2 r = *(const float2*)(res + (size_t)row * N + col);
                    x0 += r.x; x1 += r.y;
                }
                if (OUTBF) {
                    __nv_bfloat162* p = (__nv_bfloat162*)
                        ((bf16*)Cout + (size_t)row * N + col);
                    *p = __floats2bfloat162_rn(x0, x1);
                } else {
                    *(float2*)((float*)Cout + (size_t)row * N + col)
                        = make_float2(x0, x1);
                }
            }
        }
}

// ---------------------------------------------------------------------------
// Tensor-core window attention (Round-7, unchanged)
// ---------------------------------------------------------------------------
__global__ __launch_bounds__(128)
void attn_tc_kernel(const bf16* __restrict__ qkv,
                    const float* __restrict__ rpb,
                    bf16* __restrict__ O, int shifted)
{
    __shared__ bf16 Qs[64 * 40];
    __shared__ bf16 Ks[64 * 40];
    __shared__ bf16 Vs[64 * 40];
    __shared__ float rpbs[2058];
    __shared__ int tok[64];
    __shared__ int regid[64];

    int tid = threadIdx.x;
    int wq = tid >> 5, lane = tid & 31;
    int g = lane >> 2, t = lane & 3;
    int win = blockIdx.x;
    int ws = win >> 8, wh = (win >> 4) & 15, ww = win & 15;

    if (tid < 64) {
        int i = tid >> 4, j = (tid >> 2) & 3, k = tid & 3;
        int cs = ws * 4 + i, ch = wh * 4 + j, cw = ww * 4 + k;
        int sg, hg, wg;
        if (shifted) { sg = (cs + 2) & 31; hg = (ch + 2) & 63; wg = (cw + 2) & 63; }
        else         { sg = cs;            hg = ch;            wg = cw; }
        tok[tid] = (sg * 64 + hg) * 64 + wg;
        int rs = cs < 28 ? 0 : (cs < 30 ? 1 : 2);
        int rh = ch < 60 ? 0 : (ch < 62 ? 1 : 2);
        int rw = cw < 60 ? 0 : (cw < 62 ? 1 : 2);
        regid[tid] = rs * 9 + rh * 3 + rw;
    }
    for (int i = tid; i < 2058; i += 128) rpbs[i] = rpb[i];
    __syncthreads();

    int r0 = wq * 16 + g;
    int r1 = r0 + 8;
    int i0 = r0 >> 4, j0 = (r0 >> 2) & 3, k0 = r0 & 3;
    int i1 = r1 >> 4, j1 = (r1 >> 2) & 3, k1 = r1 & 3;
    int reg0 = regid[r0], reg1 = regid[r1];
    size_t ob0 = (size_t)tok[r0] * C_DIM;
    size_t ob1 = (size_t)tok[r1] * C_DIM;

    int ldrow = (lane & 7) + ((lane >> 3) & 1) * 8;
    int ldcol = (lane >> 4) * 8;
    unsigned qB = (unsigned)__cvta_generic_to_shared(Qs)
                + (unsigned)(((wq * 16 + ldrow) * 40 + ldcol) * 2);
    unsigned kB = (unsigned)__cvta_generic_to_shared(Ks)
                + (unsigned)((ldrow * 40 + ldcol) * 2);
    unsigned vB = (unsigned)__cvta_generic_to_shared(Vs)
                + (unsigned)((ldrow * 40 + ldcol) * 2);

    const float scale = 0.17677669529663687f;

    for (int h = 0; h < 6; h++) {
#pragma unroll
        for (int l = 0; l < 2; l++) {
            int idx = tid + l * 128;
            int row = idx >> 2;
            int c = (idx & 3) * 8;
            const bf16* src = qkv + (size_t)tok[row] * QKV_DIM + h * 32 + c;
            cp_async16(&Qs[row * 40 + c], src);
            cp_async16(&Ks[row * 40 + c], src + 192);
            cp_async16(&Vs[row * 40 + c], src + 384);
        }
        asm volatile("cp.async.commit_group;");
        asm volatile("cp.async.wait_group 0;");
        __syncthreads();

        float s[8][4];
#pragma unroll
        for (int j = 0; j < 8; j++)
#pragma unroll
            for (int e = 0; e < 4; e++) s[j][e] = 0.f;

#pragma unroll
        for (int ks = 0; ks < 2; ks++) {
            unsigned a0, a1, a2, a3;
            ldsm_x4(a0, a1, a2, a3, qB + ks * 32);
#pragma unroll
            for (int nc = 0; nc < 4; nc++) {
                unsigned kr0, kr1, kr2, kr3;
                ldsm_x4(kr0, kr1, kr2, kr3, kB + nc * (16 * 80) + ks * 32);
                mma16816(s[nc * 2],     a0, a1, a2, a3, kr0, kr2);
                mma16816(s[nc * 2 + 1], a0, a1, a2, a3, kr1, kr3);
            }
        }

#pragma unroll
        for (int j = 0; j < 8; j++) {
            int cb = j * 8 + 2 * t;
#pragma unroll
            for (int e = 0; e < 4; e++) {
                int m = cb + (e & 1);
                int im = m >> 4, jm = (m >> 2) & 3, km = m & 3;
                float val;
                if (e < 2) {
                    int idx = (i0 - im + 3) * 49 + (j0 - jm + 3) * 7 + (k0 - km + 3);
                    val = s[j][e] * scale + rpbs[idx * 6 + h];
                    if (shifted && (reg0 != regid[m])) val -= 100.f;
                } else {
                    int idx = (i1 - im + 3) * 49 + (j1 - jm + 3) * 7 + (k1 - km + 3);
                    val = s[j][e] * scale + rpbs[idx * 6 + h];
                    if (shifted && (reg1 != regid[m])) val -= 100.f;
                }
                s[j][e] = val;
            }
        }

        float mx0 = -1e30f, mx1 = -1e30f;
#pragma unroll
        for (int j = 0; j < 8; j++) {
            mx0 = fmaxf(mx0, fmaxf(s[j][0], s[j][1]));
            mx1 = fmaxf(mx1, fmaxf(s[j][2], s[j][3]));
        }
        mx0 = fmaxf(mx0, __shfl_xor_sync(0xffffffffu, mx0, 1));
        mx0 = fmaxf(mx0, __shfl_xor_sync(0xffffffffu, mx0, 2));
        mx1 = fmaxf(mx1, __shfl_xor_sync(0xffffffffu, mx1, 1));
        mx1 = fmaxf(mx1, __shfl_xor_sync(0xffffffffu, mx1, 2));
        float sum0 = 0.f, sum1 = 0.f;
#pragma unroll
        for (int j = 0; j < 8; j++) {
            s[j][0] = __expf(s[j][0] - mx0);
            s[j][1] = __expf(s[j][1] - mx0);
            s[j][2] = __expf(s[j][2] - mx1);
            s[j][3] = __expf(s[j][3] - mx1);
            sum0 += s[j][0] + s[j][1];
            sum1 += s[j][2] + s[j][3];
        }
        sum0 += __shfl_xor_sync(0xffffffffu, sum0, 1);
        sum0 += __shfl_xor_sync(0xffffffffu, sum0, 2);
        sum1 += __shfl_xor_sync(0xffffffffu, sum1, 1);
        sum1 += __shfl_xor_sync(0xffffffffu, sum1, 2);
        float inv0 = 1.0f / sum0, inv1 = 1.0f / sum1;

        unsigned pa[4][4];
#pragma unroll
        for (int kk = 0; kk < 4; kk++) {
            __nv_bfloat162 p0 = __floats2bfloat162_rn(s[2 * kk][0],     s[2 * kk][1]);
            __nv_bfloat162 p1 = __floats2bfloat162_rn(s[2 * kk][2],     s[2 * kk][3]);
            __nv_bfloat162 p2 = __floats2bfloat162_rn(s[2 * kk + 1][0], s[2 * kk + 1][1]);
            __nv_bfloat162 p3 = __floats2bfloat162_rn(s[2 * kk + 1][2], s[2 * kk + 1][3]);
            pa[kk][0] = *(unsigned*)&p0;
            pa[kk][1] = *(unsigned*)&p1;
            pa[kk][2] = *(unsigned*)&p2;
            pa[kk][3] = *(unsigned*)&p3;
        }

        float o[4][4];
#pragma unroll
        for (int j = 0; j < 4; j++)
#pragma unroll
            for (int e = 0; e < 4; e++) o[j][e] = 0.f;

#pragma unroll
        for (int kk = 0; kk < 4; kk++) {
            unsigned v0, v1, v2, v3;
            ldsm_x4_t(v0, v1, v2, v3, vB + kk * (16 * 80));
            mma16816(o[0], pa[kk][0], pa[kk][1], pa[kk][2], pa[kk][3], v0, v1);
            mma16816(o[1], pa[kk][0], pa[kk][1], pa[kk][2], pa[kk][3], v2, v3);
            unsigned w0, w1, w2, w3;
            ldsm_x4_t(w0, w1, w2, w3, vB + kk * (16 * 80) + 32);
            mma16816(o[2], pa[kk][0], pa[kk][1], pa[kk][2], pa[kk][3], w0, w1);
            mma16816(o[3], pa[kk][0], pa[kk][1], pa[kk][2], pa[kk][3], w2, w3);
        }

#pragma unroll
        for (int nt = 0; nt < 4; nt++) {
            int col = h * 32 + nt * 8 + 2 * t;
            *(__nv_bfloat162*)(O + ob0 + col) =
                __floats2bfloat162_rn(o[nt][0] * inv0, o[nt][1] * inv0);
            *(__nv_bfloat162*)(O + ob1 + col) =
                __floats2bfloat162_rn(o[nt][2] * inv1, o[nt][3] * inv1);
        }
        __syncthreads();
    }
}

// ---------------------------------------------------------------------------
static void run_block(const float* Xin, float* Xout,
                      const float* g1, const float* b1,
                      const bf16* qw, const float* qb, const float* rpb,
                      const bf16* pw, const float* pb,
                      const float* g2, const float* b2,
                      const bf16* f1w, const float* f1b,
                      const bf16* f2w, const float* f2b,
                      int shifted,
                      bf16* bufA, bf16* qkv, bf16* obuf, bf16* bufT)
{
    dim3 lnBlk(32, 8);
    int lnGrid = L_TOK / 8;

    ln_kernel<<<lnGrid, lnBlk>>>(Xin, g1, b1, bufA);
    gemm_bf16<false, false, true><<<dim3(QKV_DIM / GBN, L_TOK / GBM), 256, GSMEM>>>(
        bufA, qw, qb, nullptr, qkv, L_TOK, QKV_DIM, C_DIM);
    attn_tc_kernel<<<NWIN, 128>>>(qkv, rpb, obuf, shifted);
    gemm_bf16<false, true, false><<<dim3(C_DIM / GBN, L_TOK / GBM), 256, GSMEM>>>(
        obuf, pw, pb, Xin, Xout, L_TOK, C_DIM, C_DIM);
    ln_kernel<<<lnGrid, lnBlk>>>(Xout, g2, b2, bufA);
    gemm_bf16<true, false, true><<<dim3(FF_DIM / GBN, L_TOK / GBM), 256, GSMEM>>>(
        bufA, f1w, f1b, nullptr, bufT, L_TOK, FF_DIM, C_DIM);
    gemm_bf16<false, true, false><<<dim3(C_DIM / GBN, L_TOK / GBM), 256, GSMEM>>>(
        bufT, f2w, f2b, Xout, Xout, L_TOK, C_DIM, FF_DIM);
}

extern "C" void kernel_launch(void* const* d_in, const int* in_sizes, int n_in,
                              void* d_out, int out_size)
{
    (void)in_sizes; (void)n_in; (void)out_size;
    const float* x = (const float*)d_in[0];
    float* out = (float*)d_out;

    bf16 *bufA, *qkv, *obuf, *bufT, *wbf;
    cudaGetSymbolAddress((void**)&bufA, g_bufA);
    cudaGetSymbolAddress((void**)&qkv,  g_qkv);
    cudaGetSymbolAddress((void**)&obuf, g_obuf);
    cudaGetSymbolAddress((void**)&bufT, g_bufT);
    cudaGetSymbolAddress((void**)&wbf,  g_wbf);

    cudaFuncSetAttribute(gemm_bf16<false, false, true>,
                         cudaFuncAttributeMaxDynamicSharedMemorySize, GSMEM);
    cudaFuncSetAttribute(gemm_bf16<false, true, false>,
                         cudaFuncAttributeMaxDynamicSharedMemorySize, GSMEM);
    cudaFuncSetAttribute(gemm_bf16<true, false, true>,
                         cudaFuncAttributeMaxDynamicSharedMemorySize, GSMEM);

    const int SZ_QW = C_DIM * QKV_DIM;
    const int SZ_PW = C_DIM * C_DIM;
    const int SZ_F1 = C_DIM * FF_DIM;
    const int SZ_F2 = FF_DIM * C_DIM;

    const int widx[8] = { 3, 6, 10, 12, 16, 19, 23, 25 };
    const int wsz [8] = { SZ_QW, SZ_PW, SZ_F1, SZ_F2, SZ_QW, SZ_PW, SZ_F1, SZ_F2 };

    WcvtArgs wa;
    int off = 0;
    bf16* wp[8];
    for (int i = 0; i < 8; i++) {
        wa.src[i] = (const float*)d_in[widx[i]];
        wa.off[i] = off;
        wp[i] = wbf + off;
        off += wsz[i];
    }
    wa.off[8] = off;
    cvt_weights_kernel<<<(off + 255) / 256, 256>>>(wa, wbf);

    run_block(x, out,
              (const float*)d_in[1],  (const float*)d_in[2],
              wp[0],                  (const float*)d_in[4],  (const float*)d_in[5],
              wp[1],                  (const float*)d_in[7],
              (const float*)d_in[8],  (const float*)d_in[9],
              wp[2],                  (const float*)d_in[11],
              wp[3],                  (const float*)d_in[13],
              0, bufA, qkv, obuf, bufT);

    run_block(out, out,
              (const float*)d_in[14], (const float*)d_in[15],
              wp[4],                  (const float*)d_in[17], (const float*)d_in[18],
              wp[5],                  (const float*)d_in[20],
              (const float*)d_in[21], (const float*)d_in[22],
              wp[6],                  (const float*)d_in[24],
              wp[7],                  (const float*)d_in[26],
              1, bufA, qkv, obuf, bufT);
}

// round 15
// speedup vs baseline: 1.2586x; 1.2586x over previous
#include <cuda_runtime.h>
#include <cuda_bf16.h>
#include <math.h>

#define L_TOK 131072
#define C_DIM 192
#define QKV_DIM 576
#define FF_DIM 768
#define NWIN 2048

typedef __nv_bfloat16 bf16;

// scratch (device globals)
__device__ bf16 g_bufA[(size_t)L_TOK * C_DIM];   // LN out (bf16)
__device__ bf16 g_qkv [(size_t)L_TOK * QKV_DIM]; // QKV (bf16)
__device__ bf16 g_obuf[(size_t)L_TOK * C_DIM];   // attn out (bf16)
__device__ bf16 g_bufT[(size_t)L_TOK * FF_DIM];  // MLP hidden (bf16)
__device__ bf16 g_wbf [884736];                  // bf16 weights [K,N]

__device__ __forceinline__ void cp_async16(void* smem, const void* gmem) {
    unsigned saddr = (unsigned)__cvta_generic_to_shared(smem);
    asm volatile("cp.async.cg.shared.global [%0], [%1], 16;\n" :: "r"(saddr), "l"(gmem));
}
__device__ __forceinline__ void ldsm_x4(unsigned& r0, unsigned& r1,
                                        unsigned& r2, unsigned& r3, unsigned addr) {
    asm volatile("ldmatrix.sync.aligned.m8n8.x4.shared.b16 {%0,%1,%2,%3}, [%4];"
                 : "=r"(r0), "=r"(r1), "=r"(r2), "=r"(r3) : "r"(addr));
}
__device__ __forceinline__ void ldsm_x4_t(unsigned& r0, unsigned& r1,
                                          unsigned& r2, unsigned& r3, unsigned addr) {
    asm volatile("ldmatrix.sync.aligned.m8n8.x4.trans.shared.b16 {%0,%1,%2,%3}, [%4];"
                 : "=r"(r0), "=r"(r1), "=r"(r2), "=r"(r3) : "r"(addr));
}
__device__ __forceinline__ void mma16816(float* c, unsigned a0, unsigned a1,
                                         unsigned a2, unsigned a3,
                                         unsigned b0, unsigned b1) {
    asm volatile(
        "mma.sync.aligned.m16n8k16.row.col.f32.bf16.bf16.f32 "
        "{%0,%1,%2,%3},{%4,%5,%6,%7},{%8,%9},{%0,%1,%2,%3};"
        : "+f"(c[0]), "+f"(c[1]), "+f"(c[2]), "+f"(c[3])
        : "r"(a0), "r"(a1), "r"(a2), "r"(a3), "r"(b0), "r"(b1));
}

// ---------------------------------------------------------------------------
// Fused weight conversion
// ---------------------------------------------------------------------------
struct WcvtArgs {
    const float* src[8];
    int off[9];
};

__global__ void cvt_weights_kernel(WcvtArgs a, bf16* __restrict__ out)
{
    int i = blockIdx.x * 256 + threadIdx.x;
    if (i >= a.off[8]) return;
    int s = 0;
#pragma unroll
    for (int j = 1; j < 8; j++) s += (i >= a.off[j]);
    out[i] = __float2bfloat16(a.src[s][i - a.off[s]]);
}

// ---------------------------------------------------------------------------
// LayerNorm, one row per warp; bf16 output
// ---------------------------------------------------------------------------
__global__ void ln_kernel(const float* __restrict__ x,
                          const float* __restrict__ g,
                          const float* __restrict__ b,
                          bf16* __restrict__ out)
{
    int row  = blockIdx.x * 8 + threadIdx.y;
    int lane = threadIdx.x;
    const float* xr = x + (size_t)row * C_DIM;
    float v[6];
    float s = 0.f;
#pragma unroll
    for (int i = 0; i < 6; i++) { v[i] = xr[lane + i * 32]; s += v[i]; }
#pragma unroll
    for (int o = 16; o; o >>= 1) s += __shfl_xor_sync(0xffffffffu, s, o);
    float mu = s * (1.0f / 192.0f);
    float vs = 0.f;
#pragma unroll
    for (int i = 0; i < 6; i++) { float d = v[i] - mu; vs += d * d; }
#pragma unroll
    for (int o = 16; o; o >>= 1) vs += __shfl_xor_sync(0xffffffffu, vs, o);
    float rstd = rsqrtf(vs * (1.0f / 192.0f) + 1e-5f);
    bf16* orow = out + (size_t)row * C_DIM;
#pragma unroll
    for (int i = 0; i < 6; i++) {
        int c = lane + i * 32;
        orow[c] = __float2bfloat16((v[i] - mu) * rstd * g[c] + b[c]);
    }
}

// ---------------------------------------------------------------------------
// bf16 GEMM (Round-13 proven): BM=128, BN=192, BK=64. 256 thr, 8 warps
// (4m x 2n), warp tile 32x96. 3-stage cp.async ring, ONE sync per iter.
// Dynamic smem 132 KB, 1 CTA/SM.
// ---------------------------------------------------------------------------
#define GBM 128
#define GBN 192
#define GBK 64
#define ASTRH 72                      // 64 + 8 pad (bf16)
#define BSTRH 200                     // 192 + 8 pad (bf16)
#define ABYTES (GBM * ASTRH * 2)      // 18432
#define BBYTES (GBK * BSTRH * 2)      // 25600
#define STAGEB (ABYTES + BBYTES)      // 44032
#define NSTAGE 3
#define GSMEM  (NSTAGE * STAGEB)      // 132096

template<bool DOGELU, bool RES, bool OUTBF>
__global__ __launch_bounds__(256, 1)
void gemm_bf16(const bf16* __restrict__ A, const bf16* __restrict__ B,
               const float* __restrict__ bias, const float* __restrict__ res,
               void* __restrict__ Cout, int M, int N, int K)
{
    extern __shared__ char smem[];

    int tid = threadIdx.x;
    int bm = blockIdx.y * GBM;
    int bn = blockIdx.x * GBN;
    int wid = tid >> 5, lane = tid & 31;
    int wm = (wid & 3) * 32, wn = (wid >> 2) * 96;
    int g = lane >> 2, t = lane & 3;

    int ldrow = (lane & 7) + ((lane >> 3) & 1) * 8;
    int ldcol = (lane >> 4) * 8;

    unsigned s0 = (unsigned)__cvta_generic_to_shared(smem);
    unsigned aBase = s0 + (unsigned)(((wm + ldrow) * ASTRH + ldcol) * 2);
    unsigned bBase = s0 + (unsigned)(ABYTES + (ldrow * BSTRH + wn + ldcol) * 2);

    float acc[2][12][4];
#pragma unroll
    for (int a = 0; a < 2; a++)
#pragma unroll
        for (int j = 0; j < 12; j++)
#pragma unroll
            for (int c = 0; c < 4; c++) acc[a][j][c] = 0.f;

    auto loadA = [&](int stage, int k0) {
#pragma unroll
        for (int l = 0; l < 4; l++) {
            int idx = tid + l * 256;
            int m = idx >> 3;
            int c = (idx & 7) * 8;
            cp_async16(smem + stage * STAGEB + (m * ASTRH + c) * 2,
                       A + (size_t)(bm + m) * K + k0 + c);
        }
    };
    auto loadB = [&](int stage, int k0) {
#pragma unroll
        for (int l = 0; l < 6; l++) {
            int idx = tid + l * 256;
            int r = idx / 24;
            int c = (idx % 24) * 8;
            cp_async16(smem + stage * STAGEB + ABYTES + (r * BSTRH + c) * 2,
                       B + (size_t)(k0 + r) * N + bn + c);
        }
    };

    int nk = K / GBK;
    loadA(0, 0); loadB(0, 0);
    asm volatile("cp.async.commit_group;");
    if (nk > 1) { loadA(1, GBK); loadB(1, GBK); }
    asm volatile("cp.async.commit_group;");

    for (int kb = 0; kb < nk; kb++) {
        if (kb + 1 < nk) { asm volatile("cp.async.wait_group 1;"); }
        else             { asm volatile("cp.async.wait_group 0;"); }
        __syncthreads();

        if (kb + 2 < nk) {
            loadA((kb + 2) % NSTAGE, (kb + 2) * GBK);
            loadB((kb + 2) % NSTAGE, (kb + 2) * GBK);
            asm volatile("cp.async.commit_group;");
        }

        int st = kb % NSTAGE;
        unsigned aS = aBase + st * STAGEB;
        unsigned bS = bBase + st * STAGEB;
#pragma unroll
        for (int ks = 0; ks < 4; ks++) {
            unsigned af[2][4], bfr[6][4];
#pragma unroll
            for (int mt = 0; mt < 2; mt++)
                ldsm_x4(af[mt][0], af[mt][1], af[mt][2], af[mt][3],
                        aS + mt * (16 * ASTRH * 2) + ks * 32);
#pragma unroll
            for (int nt = 0; nt < 6; nt++)
                ldsm_x4_t(bfr[nt][0], bfr[nt][1], bfr[nt][2], bfr[nt][3],
                          bS + ks * (16 * BSTRH * 2) + nt * 32);
#pragma unroll
            for (int mt = 0; mt < 2; mt++)
#pragma unroll
                for (int nt = 0; nt < 6; nt++) {
                    mma16816(acc[mt][nt * 2],     af[mt][0], af[mt][1],
                             af[mt][2], af[mt][3], bfr[nt][0], bfr[nt][1]);
                    mma16816(acc[mt][nt * 2 + 1], af[mt][0], af[mt][1],
                             af[mt][2], af[mt][3], bfr[nt][2], bfr[nt][3]);
                }
        }
    }

#pragma unroll
    for (int mt = 0; mt < 2; mt++)
#pragma unroll
        for (int j = 0; j < 12; j++) {
            int col = bn + wn + j * 8 + 2 * t;
            float2 bv = *(const float2*)(bias + col);
#pragma unroll
            for (int hf = 0; hf < 2; hf++) {
                int row = bm + wm + mt * 16 + g + hf * 8;
                float x0 = acc[mt][j][hf * 2 + 0] + bv.x;
                float x1 = acc[mt][j][hf * 2 + 1] + bv.y;
                if (DOGELU) {
                    x0 = 0.5f * x0 * (1.0f + erff(x0 * 0.70710678118654752f));
                    x1 = 0.5f * x1 * (1.0f + erff(x1 * 0.70710678118654752f));
                }
                if (RES) {
                    float2 r = *(const float2*)(res + (size_t)row * N + col);
                    x0 += r.x; x1 += r.y;
                }
                if (OUTBF) {
                    __nv_bfloat162* p = (__nv_bfloat162*)
                        ((bf16*)Cout + (size_t)row * N + col);
                    *p = __floats2bfloat162_rn(x0, x1);
                } else {
                    *(float2*)((float*)Cout + (size_t)row * N + col)
                        = make_float2(x0, x1);
                }
            }
        }
}

// ---------------------------------------------------------------------------
// Tensor-core window attention, DOUBLE-BUFFERED head loop.
// Smem: 2*3*5120 + 8232 + 512 = ~39.5 KB.
// ---------------------------------------------------------------------------
__global__ __launch_bounds__(128)
void attn_tc_kernel(const bf16* __restrict__ qkv,
                    const float* __restrict__ rpb,
                    bf16* __restrict__ O, int shifted)
{
    __shared__ bf16 Qs[2][64 * 40];
    __shared__ bf16 Ks[2][64 * 40];
    __shared__ bf16 Vs[2][64 * 40];
    __shared__ float rpbs[2058];
    __shared__ int tok[64];
    __shared__ int regid[64];

    int tid = threadIdx.x;
    int wq = tid >> 5, lane = tid & 31;
    int g = lane >> 2, t = lane & 3;
    int win = blockIdx.x;
    int ws = win >> 8, wh = (win >> 4) & 15, ww = win & 15;

    if (tid < 64) {
        int i = tid >> 4, j = (tid >> 2) & 3, k = tid & 3;
        int cs = ws * 4 + i, ch = wh * 4 + j, cw = ww * 4 + k;
        int sg, hg, wg;
        if (shifted) { sg = (cs + 2) & 31; hg = (ch + 2) & 63; wg = (cw + 2) & 63; }
        else         { sg = cs;            hg = ch;            wg = cw; }
        tok[tid] = (sg * 64 + hg) * 64 + wg;
        int rs = cs < 28 ? 0 : (cs < 30 ? 1 : 2);
        int rh = ch < 60 ? 0 : (ch < 62 ? 1 : 2);
        int rw = cw < 60 ? 0 : (cw < 62 ? 1 : 2);
        regid[tid] = rs * 9 + rh * 3 + rw;
    }
    for (int i = tid; i < 2058; i += 128) rpbs[i] = rpb[i];
    __syncthreads();

    int r0 = wq * 16 + g;
    int r1 = r0 + 8;
    int i0 = r0 >> 4, j0 = (r0 >> 2) & 3, k0 = r0 & 3;
    int i1 = r1 >> 4, j1 = (r1 >> 2) & 3, k1 = r1 & 3;
    int reg0 = regid[r0], reg1 = regid[r1];
    size_t ob0 = (size_t)tok[r0] * C_DIM;
    size_t ob1 = (size_t)tok[r1] * C_DIM;

    int ldrow = (lane & 7) + ((lane >> 3) & 1) * 8;
    int ldcol = (lane >> 4) * 8;
    unsigned qB0 = (unsigned)__cvta_generic_to_shared(&Qs[0][0])
                 + (unsigned)(((wq * 16 + ldrow) * 40 + ldcol) * 2);
    unsigned kB0 = (unsigned)__cvta_generic_to_shared(&Ks[0][0])
                 + (unsigned)((ldrow * 40 + ldcol) * 2);
    unsigned vB0 = (unsigned)__cvta_generic_to_shared(&Vs[0][0])
                 + (unsigned)((ldrow * 40 + ldcol) * 2);
    const unsigned BUFB = 64 * 40 * 2;   // bytes per buffer

    const float scale = 0.17677669529663687f;

    // my two load rows (row = tid>>1, col chunk = (tid&1)*16 .. +8) : 2 per thread
    auto load_head = [&](int buf, int h) {
#pragma unroll
        for (int l = 0; l < 2; l++) {
            int idx = tid + l * 128;
            int row = idx >> 2;
            int c = (idx & 3) * 8;
            const bf16* src = qkv + (size_t)tok[row] * QKV_DIM + h * 32 + c;
            cp_async16(&Qs[buf][row * 40 + c], src);
            cp_async16(&Ks[buf][row * 40 + c], src + 192);
            cp_async16(&Vs[buf][row * 40 + c], src + 384);
        }
        asm volatile("cp.async.commit_group;");
    };

    load_head(0, 0);

    for (int h = 0; h < 6; h++) {
        int buf = h & 1;
        asm volatile("cp.async.wait_group 0;");
        __syncthreads();                       // buf[h&1] ready for all warps

        if (h + 1 < 6) load_head((h + 1) & 1, h + 1);   // overlap with compute

        unsigned qB = qB0 + buf * BUFB;
        unsigned kB = kB0 + buf * BUFB;
        unsigned vB = vB0 + buf * BUFB;

        float s[8][4];
#pragma unroll
        for (int j = 0; j < 8; j++)
#pragma unroll
            for (int e = 0; e < 4; e++) s[j][e] = 0.f;

#pragma unroll
        for (int ks = 0; ks < 2; ks++) {
            unsigned a0, a1, a2, a3;
            ldsm_x4(a0, a1, a2, a3, qB + ks * 32);
#pragma unroll
            for (int nc = 0; nc < 4; nc++) {
                unsigned kr0, kr1, kr2, kr3;
                ldsm_x4(kr0, kr1, kr2, kr3, kB + nc * (16 * 80) + ks * 32);
                mma16816(s[nc * 2],     a0, a1, a2, a3, kr0, kr2);
                mma16816(s[nc * 2 + 1], a0, a1, a2, a3, kr1, kr3);
            }
        }

#pragma unroll
        for (int j = 0; j < 8; j++) {
            int cb = j * 8 + 2 * t;
#pragma unroll
            for (int e = 0; e < 4; e++) {
                int m = cb + (e & 1);
                int im = m >> 4, jm = (m >> 2) & 3, km = m & 3;
                float val;
                if (e < 2) {
                    int idx = (i0 - im + 3) * 49 + (j0 - jm + 3) * 7 + (k0 - km + 3);
                    val = s[j][e] * scale + rpbs[idx * 6 + h];
                    if (shifted && (reg0 != regid[m])) val -= 100.f;
                } else {
                    int idx = (i1 - im + 3) * 49 + (j1 - jm + 3) * 7 + (k1 - km + 3);
                    val = s[j][e] * scale + rpbs[idx * 6 + h];
                    if (shifted && (reg1 != regid[m])) val -= 100.f;
                }
                s[j][e] = val;
            }
        }

        float mx0 = -1e30f, mx1 = -1e30f;
#pragma unroll
        for (int j = 0; j < 8; j++) {
            mx0 = fmaxf(mx0, fmaxf(s[j][0], s[j][1]));
            mx1 = fmaxf(mx1, fmaxf(s[j][2], s[j][3]));
        }
        mx0 = fmaxf(mx0, __shfl_xor_sync(0xffffffffu, mx0, 1));
        mx0 = fmaxf(mx0, __shfl_xor_sync(0xffffffffu, mx0, 2));
        mx1 = fmaxf(mx1, __shfl_xor_sync(0xffffffffu, mx1, 1));
        mx1 = fmaxf(mx1, __shfl_xor_sync(0xffffffffu, mx1, 2));
        float sum0 = 0.f, sum1 = 0.f;
#pragma unroll
        for (int j = 0; j < 8; j++) {
            s[j][0] = __expf(s[j][0] - mx0);
            s[j][1] = __expf(s[j][1] - mx0);
            s[j][2] = __expf(s[j][2] - mx1);
            s[j][3] = __expf(s[j][3] - mx1);
            sum0 += s[j][0] + s[j][1];
            sum1 += s[j][2] + s[j][3];
        }
        sum0 += __shfl_xor_sync(0xffffffffu, sum0, 1);
        sum0 += __shfl_xor_sync(0xffffffffu, sum0, 2);
        sum1 += __shfl_xor_sync(0xffffffffu, sum1, 1);
        sum1 += __shfl_xor_sync(0xffffffffu, sum1, 2);
        float inv0 = 1.0f / sum0, inv1 = 1.0f / sum1;

        unsigned pa[4][4];
#pragma unroll
        for (int kk = 0; kk < 4; kk++) {
            __nv_bfloat162 p0 = __floats2bfloat162_rn(s[2 * kk][0],     s[2 * kk][1]);
            __nv_bfloat162 p1 = __floats2bfloat162_rn(s[2 * kk][2],     s[2 * kk][3]);
            __nv_bfloat162 p2 = __floats2bfloat162_rn(s[2 * kk + 1][0], s[2 * kk + 1][1]);
            __nv_bfloat162 p3 = __floats2bfloat162_rn(s[2 * kk + 1][2], s[2 * kk + 1][3]);
            pa[kk][0] = *(unsigned*)&p0;
            pa[kk][1] = *(unsigned*)&p1;
            pa[kk][2] = *(unsigned*)&p2;
            pa[kk][3] = *(unsigned*)&p3;
        }

        float o[4][4];
#pragma unroll
        for (int j = 0; j < 4; j++)
#pragma unroll
            for (int e = 0; e < 4; e++) o[j][e] = 0.f;

#pragma unroll
        for (int kk = 0; kk < 4; kk++) {
            unsigned v0, v1, v2, v3;
            ldsm_x4_t(v0, v1, v2, v3, vB + kk * (16 * 80));
            mma16816(o[0], pa[kk][0], pa[kk][1], pa[kk][2], pa[kk][3], v0, v1);
            mma16816(o[1], pa[kk][0], pa[kk][1], pa[kk][2], pa[kk][3], v2, v3);
            unsigned w0, w1, w2, w3;
            ldsm_x4_t(w0, w1, w2, w3, vB + kk * (16 * 80) + 32);
            mma16816(o[2], pa[kk][0], pa[kk][1], pa[kk][2], pa[kk][3], w0, w1);
            mma16816(o[3], pa[kk][0], pa[kk][1], pa[kk][2], pa[kk][3], w2, w3);
        }

#pragma unroll
        for (int nt = 0; nt < 4; nt++) {
            int col = h * 32 + nt * 8 + 2 * t;
            *(__nv_bfloat162*)(O + ob0 + col) =
                __floats2bfloat162_rn(o[nt][0] * inv0, o[nt][1] * inv0);
            *(__nv_bfloat162*)(O + ob1 + col) =
                __floats2bfloat162_rn(o[nt][2] * inv1, o[nt][3] * inv1);
        }
        __syncthreads();   // compute(h) done before load(h+2) reuses buf
    }
}

// ---------------------------------------------------------------------------
static void run_block(const float* Xin, float* Xout,
                      const float* g1, const float* b1,
                      const bf16* qw, const float* qb, const float* rpb,
                      const bf16* pw, const float* pb,
                      const float* g2, const float* b2,
                      const bf16* f1w, const float* f1b,
                      const bf16* f2w, const float* f2b,
                      int shifted,
                      bf16* bufA, bf16* qkv, bf16* obuf, bf16* bufT)
{
    dim3 lnBlk(32, 8);
    int lnGrid = L_TOK / 8;

    ln_kernel<<<lnGrid, lnBlk>>>(Xin, g1, b1, bufA);
    gemm_bf16<false, false, true><<<dim3(QKV_DIM / GBN, L_TOK / GBM), 256, GSMEM>>>(
        bufA, qw, qb, nullptr, qkv, L_TOK, QKV_DIM, C_DIM);
    attn_tc_kernel<<<NWIN, 128>>>(qkv, rpb, obuf, shifted);
    gemm_bf16<false, true, false><<<dim3(C_DIM / GBN, L_TOK / GBM), 256, GSMEM>>>(
        obuf, pw, pb, Xin, Xout, L_TOK, C_DIM, C_DIM);
    ln_kernel<<<lnGrid, lnBlk>>>(Xout, g2, b2, bufA);
    gemm_bf16<true, false, true><<<dim3(FF_DIM / GBN, L_TOK / GBM), 256, GSMEM>>>(
        bufA, f1w, f1b, nullptr, bufT, L_TOK, FF_DIM, C_DIM);
    gemm_bf16<false, true, false><<<dim3(C_DIM / GBN, L_TOK / GBM), 256, GSMEM>>>(
        bufT, f2w, f2b, Xout, Xout, L_TOK, C_DIM, FF_DIM);
}

extern "C" void kernel_launch(void* const* d_in, const int* in_sizes, int n_in,
                              void* d_out, int out_size)
{
    (void)in_sizes; (void)n_in; (void)out_size;
    const float* x = (const float*)d_in[0];
    float* out = (float*)d_out;

    bf16 *bufA, *qkv, *obuf, *bufT, *wbf;
    cudaGetSymbolAddress((void**)&bufA, g_bufA);
    cudaGetSymbolAddress((void**)&qkv,  g_qkv);
    cudaGetSymbolAddress((void**)&obuf, g_obuf);
    cudaGetSymbolAddress((void**)&bufT, g_bufT);
    cudaGetSymbolAddress((void**)&wbf,  g_wbf);

    cudaFuncSetAttribute(gemm_bf16<false, false, true>,
                         cudaFuncAttributeMaxDynamicSharedMemorySize, GSMEM);
    cudaFuncSetAttribute(gemm_bf16<false, true, false>,
                         cudaFuncAttributeMaxDynamicSharedMemorySize, GSMEM);
    cudaFuncSetAttribute(gemm_bf16<true, false, true>,
                         cudaFuncAttributeMaxDynamicSharedMemorySize, GSMEM);

    const int SZ_QW = C_DIM * QKV_DIM;
    const int SZ_PW = C_DIM * C_DIM;
    const int SZ_F1 = C_DIM * FF_DIM;
    const int SZ_F2 = FF_DIM * C_DIM;

    const int widx[8] = { 3, 6, 10, 12, 16, 19, 23, 25 };
    const int wsz [8] = { SZ_QW, SZ_PW, SZ_F1, SZ_F2, SZ_QW, SZ_PW, SZ_F1, SZ_F2 };

    WcvtArgs wa;
    int off = 0;
    bf16* wp[8];
    for (int i = 0; i < 8; i++) {
        wa.src[i] = (const float*)d_in[widx[i]];
        wa.off[i] = off;
        wp[i] = wbf + off;
        off += wsz[i];
    }
    wa.off[8] = off;
    cvt_weights_kernel<<<(off + 255) / 256, 256>>>(wa, wbf);

    run_block(x, out,
              (const float*)d_in[1],  (const float*)d_in[2],
              wp[0],                  (const float*)d_in[4],  (const float*)d_in[5],
              wp[1],                  (const float*)d_in[7],
              (const float*)d_in[8],  (const float*)d_in[9],
              wp[2],                  (const float*)d_in[11],
              wp[3],                  (const float*)d_in[13],
              0, bufA, qkv, obuf, bufT);

    run_block(out, out,
              (const float*)d_in[14], (const float*)d_in[15],
              wp[4],                  (const float*)d_in[17], (const float*)d_in[18],
              wp[5],                  (const float*)d_in[20],
              (const float*)d_in[21], (const float*)d_in[22],
              wp[6],                  (const float*)d_in[24],
              wp[7],                  (const float*)d_in[26],
              1, bufA, qkv, obuf, bufT);
}